// round 15
// baseline (speedup 1.0000x reference)
#include <cuda_runtime.h>
#include <cstdint>

#define B_  8
#define C_  64
#define CQ_ 8
#define H_  128
#define W_  128
#define HW_ (H_*W_)            // 16384
#define NPIX_ (B_*HW_)         // 131072
#define NELEM_ (B_*C_*HW_)     // 8388608

typedef unsigned long long u64;

// ---- packed fp32x2 helpers ----
__device__ __forceinline__ u64 fma2(u64 a, u64 b, u64 c) {
    u64 d; asm("fma.rn.f32x2 %0, %1, %2, %3;" : "=l"(d) : "l"(a), "l"(b), "l"(c));
    return d;
}
__device__ __forceinline__ u64 add2(u64 a, u64 b) {
    u64 d; asm("add.rn.f32x2 %0, %1, %2;" : "=l"(d) : "l"(a), "l"(b));
    return d;
}
__device__ __forceinline__ u64 pack2(float lo, float hi) {
    u64 d; asm("mov.b64 %0, {%1, %2};" : "=l"(d) : "f"(lo), "f"(hi));
    return d;
}
__device__ __forceinline__ void unpack2(u64 a, float& lo, float& hi) {
    asm("mov.b64 {%0, %1}, %2;" : "=f"(lo), "=f"(hi) : "l"(a));
}

// ---- tf32 helpers ----
__device__ __forceinline__ uint32_t tf32r(float f) {
    uint32_t r; asm("cvt.rna.tf32.f32 %0, %1;" : "=r"(r) : "f"(f));
    return r;
}
__device__ __forceinline__ float tf32f(float f) {
    return __uint_as_float(tf32r(f));
}
__device__ __forceinline__ void mma_tf32(float* d,
    uint32_t a0, uint32_t a1, uint32_t a2, uint32_t a3,
    uint32_t b0, uint32_t b1) {
    asm("mma.sync.aligned.m16n8k8.row.col.f32.tf32.tf32.f32 "
        "{%0,%1,%2,%3}, {%4,%5,%6,%7}, {%8,%9}, {%0,%1,%2,%3};"
        : "+f"(d[0]), "+f"(d[1]), "+f"(d[2]), "+f"(d[3])
        : "r"(a0), "r"(a1), "r"(a2), "r"(a3), "r"(b0), "r"(b1));
}

// ---- scratch (device globals; no allocation allowed) ----
__device__ float g_y[NELEM_];
__device__ float g_y2[NELEM_];
__device__ float g_yT[NELEM_];
__device__ float g_accW[NELEM_];
__device__ float g_accHT[NELEM_];
__device__ float g_lW[NPIX_];
__device__ float g_lHT[NPIX_];

// ---------------- depthwise 3x3 conv, pad 1; emits y AND yT ----------------
__global__ void __launch_bounds__(256) dwconv_kernel(
    const float* __restrict__ x, const float* __restrict__ wdw,
    float* __restrict__ y, float* __restrict__ yT) {
    __shared__ float tile[34][35];
    __shared__ float oT[32][33];
    int p = blockIdx.z;                 // b*C + c
    int c = p & 63;
    int h0 = blockIdx.y * 32, w0 = blockIdx.x * 32;
    int tx = threadIdx.x, ty = threadIdx.y;
    int tid = ty * 32 + tx;
    float wr[9];
#pragma unroll
    for (int i = 0; i < 9; i++) wr[i] = wdw[c * 9 + i];
    const float* xp = x + p * HW_;
#pragma unroll
    for (int idx = tid; idx < 34 * 34; idx += 256) {
        int i = idx / 34, j = idx % 34;
        int hh = h0 - 1 + i, ww = w0 - 1 + j;
        tile[i][j] = (hh >= 0 && hh < 128 && ww >= 0 && ww < 128)
                     ? xp[hh * 128 + ww] : 0.f;
    }
    __syncthreads();
    float* yp = y + p * HW_;
#pragma unroll
    for (int r = 0; r < 4; r++) {
        int i = ty + 8 * r;
        float s = 0.f;
#pragma unroll
        for (int di = 0; di < 3; di++)
#pragma unroll
            for (int dj = 0; dj < 3; dj++)
                s += tile[i + di][tx + dj] * wr[di * 3 + dj];
        yp[(h0 + i) * 128 + w0 + tx] = s;
        oT[i][tx] = s;
    }
    __syncthreads();
    float* ypT = yT + p * HW_;
#pragma unroll
    for (int r = 0; r < 4; r++)
        ypT[(w0 + ty + 8 * r) * 128 + h0 + tx] = oT[tx][ty + 8 * r];
}

// ---------------- fully-mma fused projection + directional attention ------
// Merged W+H: blockIdx.x < 1024 -> W-direction (inA, no mask);
//             else              -> H-direction (inB, diag mask).
// smem: region1 [0,14144): yS[64][136] | wvS[64][68] | wS[16][68]
//       after projection sync: svT[128][72] at [0,9216), sqk[128][20] at [9216,11776)
#define REG1_F 14144
#define ATTN_SMEM_FLOATS REG1_F            // 14144 fl = 56576 B
__global__ void __launch_bounds__(256, 4) attn_kernel(
    const float* __restrict__ inA, const float* __restrict__ inB,
    const float* __restrict__ wq, const float* __restrict__ wk,
    const float* __restrict__ wv,
    float* __restrict__ accA, float* __restrict__ accB,
    float* __restrict__ lA_out, float* __restrict__ lB_out) {
    extern __shared__ float smem[];
    float* yS  = smem;                       // [64][136]
    float* wvS = smem + 8704;                // [64][68]
    float* wS  = smem + 13056;               // [16][68]: q rows 0-7, k rows 8-15
    float (*svT)[72] = (float(*)[72])smem;   // aliases yS after projection
    float* sqk = smem + 9216;                // [128][20], after projection sync

    int half = blockIdx.x >> 10;
    int bh = blockIdx.x & 1023;
    const float* y = half ? inB : inA;
    float* acc_out = half ? accB : accA;
    float* l_out   = half ? lB_out : lA_out;
    int mask_diag  = half;

    int b = bh >> 7, r = bh & 127;
    int tid = threadIdx.x;
    int lane = tid & 31, wrp = tid >> 5;
    int gid = lane >> 2, tig = lane & 3;
    int t0 = wrp * 16;

    // ---- Stage 0: weights (tf32-rounded) + y row ----
#pragma unroll
    for (int i = tid; i < 1024; i += 256) {
        float w = (i < 512) ? wq[i] : wk[i - 512];
        int o = i >> 6, ci = i & 63;
        wS[o * 68 + ci] = tf32f(w);
    }
#pragma unroll
    for (int i = tid; i < 4096; i += 256) {
        int c = i >> 6, ci = i & 63;
        wvS[c * 68 + ci] = tf32f(wv[i]);
    }
    const float* yb = y + b * C_ * HW_ + r * W_;
#pragma unroll
    for (int i = tid; i < 8192; i += 256) {
        int cin = i >> 7, t = i & 127;
        yS[cin * 136 + t] = yb[cin * HW_ + t];
    }
    __syncthreads();

    // ---- Projection: q,k,v via tf32 mma (shared A-frags from yS) ----
    float vacc[8][4];
#pragma unroll
    for (int nt = 0; nt < 8; nt++)
#pragma unroll
        for (int i = 0; i < 4; i++) vacc[nt][i] = 0.f;
    float qacc[4] = {0.f, 0.f, 0.f, 0.f};
    float kacc[4] = {0.f, 0.f, 0.f, 0.f};

#pragma unroll 1
    for (int kt = 0; kt < 8; kt++) {
        int k0 = kt * 8;
        uint32_t a0 = __float_as_uint(yS[(k0 + tig) * 136 + t0 + gid]);
        uint32_t a1 = __float_as_uint(yS[(k0 + tig) * 136 + t0 + 8 + gid]);
        uint32_t a2 = __float_as_uint(yS[(k0 + 4 + tig) * 136 + t0 + gid]);
        uint32_t a3 = __float_as_uint(yS[(k0 + 4 + tig) * 136 + t0 + 8 + gid]);
        uint32_t bq0 = __float_as_uint(wS[gid * 68 + k0 + tig]);
        uint32_t bq1 = __float_as_uint(wS[gid * 68 + k0 + 4 + tig]);
        mma_tf32(qacc, a0, a1, a2, a3, bq0, bq1);
        uint32_t bk0 = __float_as_uint(wS[(8 + gid) * 68 + k0 + tig]);
        uint32_t bk1 = __float_as_uint(wS[(8 + gid) * 68 + k0 + 4 + tig]);
        mma_tf32(kacc, a0, a1, a2, a3, bk0, bk1);
#pragma unroll
        for (int nt = 0; nt < 8; nt++) {
            uint32_t bf0 = __float_as_uint(wvS[(nt * 8 + gid) * 68 + k0 + tig]);
            uint32_t bf1 = __float_as_uint(wvS[(nt * 8 + gid) * 68 + k0 + 4 + tig]);
            mma_tf32(vacc[nt], a0, a1, a2, a3, bf0, bf1);
        }
    }
    __syncthreads();   // all region1 reads complete; svT/sqk may overwrite

    // ---- Epilogues: q,k -> sqk ; v -> svT ----
    *(float2*)&sqk[(t0 + gid) * 20 + 8 + 2 * tig]     = make_float2(qacc[0], qacc[1]);
    *(float2*)&sqk[(t0 + 8 + gid) * 20 + 8 + 2 * tig] = make_float2(qacc[2], qacc[3]);
    *(float2*)&sqk[(t0 + gid) * 20 + 2 * tig]         = make_float2(kacc[0], kacc[1]);
    *(float2*)&sqk[(t0 + 8 + gid) * 20 + 2 * tig]     = make_float2(kacc[2], kacc[3]);
#pragma unroll
    for (int nt = 0; nt < 8; nt++) {
        int cc = nt * 8 + 2 * tig;
        *(float2*)&svT[t0 + gid][cc]     = make_float2(vacc[nt][0], vacc[nt][1]);
        *(float2*)&svT[t0 + 8 + gid][cc] = make_float2(vacc[nt][2], vacc[nt][3]);
    }
    __syncthreads();

    // ---- Fused QK -> exp -> permute -> PV ----
    uint32_t qa0 = __float_as_uint(sqk[(t0 + gid) * 20 + 8 + tig]);
    uint32_t qa1 = __float_as_uint(sqk[(t0 + 8 + gid) * 20 + 8 + tig]);
    uint32_t qa2 = __float_as_uint(sqk[(t0 + gid) * 20 + 12 + tig]);
    uint32_t qa3 = __float_as_uint(sqk[(t0 + 8 + gid) * 20 + 12 + tig]);

    float acc[8][4];
#pragma unroll
    for (int n = 0; n < 8; n++)
#pragma unroll
        for (int i = 0; i < 4; i++) acc[n][i] = 0.f;
    float lA = 0.f, lB = 0.f;
    int srcA = (lane & ~3) | (tig >> 1);
    int srcB = srcA | 2;
    bool odd = tig & 1;

#pragma unroll 1
    for (int nt = 0; nt < 16; nt++) {
        int n0 = nt * 8;
        uint32_t kb0 = __float_as_uint(sqk[(n0 + gid) * 20 + tig]);
        uint32_t kb1 = __float_as_uint(sqk[(n0 + gid) * 20 + 4 + tig]);
        float e[4] = {0.f, 0.f, 0.f, 0.f};
        mma_tf32(e, qa0, qa1, qa2, qa3, kb0, kb1);
        float p0 = __expf(e[0]), p1 = __expf(e[1]);
        float p2 = __expf(e[2]), p3 = __expf(e[3]);
        if (mask_diag) {
            int c0 = n0 + 2 * tig;
            int r0 = t0 + gid, r1 = t0 + 8 + gid;
            if (c0 == r0)     p0 = 0.f;
            if (c0 + 1 == r0) p1 = 0.f;
            if (c0 == r1)     p2 = 0.f;
            if (c0 + 1 == r1) p3 = 0.f;
        }
        lA += p0 + p1; lB += p2 + p3;
        float s0 = __shfl_sync(0xffffffffu, p0, srcA);
        float s1 = __shfl_sync(0xffffffffu, p1, srcA);
        float s2 = __shfl_sync(0xffffffffu, p2, srcA);
        float s3 = __shfl_sync(0xffffffffu, p3, srcA);
        float s4 = __shfl_sync(0xffffffffu, p0, srcB);
        float s5 = __shfl_sync(0xffffffffu, p1, srcB);
        float s6 = __shfl_sync(0xffffffffu, p2, srcB);
        float s7 = __shfl_sync(0xffffffffu, p3, srcB);
        uint32_t a0 = __float_as_uint(odd ? s1 : s0);
        uint32_t a1 = __float_as_uint(odd ? s3 : s2);
        uint32_t a2 = __float_as_uint(odd ? s5 : s4);
        uint32_t a3 = __float_as_uint(odd ? s7 : s6);
#pragma unroll
        for (int n = 0; n < 8; n++) {
            uint32_t bf0 = __float_as_uint(svT[n0 + tig][n * 8 + gid]);
            uint32_t bf1 = __float_as_uint(svT[n0 + 4 + tig][n * 8 + gid]);
            mma_tf32(acc[n], a0, a1, a2, a3, bf0, bf1);
        }
    }

    // ---- l reduction (across tig) + stores ----
    lA += __shfl_xor_sync(0xffffffffu, lA, 1);
    lA += __shfl_xor_sync(0xffffffffu, lA, 2);
    lB += __shfl_xor_sync(0xffffffffu, lB, 1);
    lB += __shfl_xor_sync(0xffffffffu, lB, 2);
    if (tig == 0) {
        l_out[b * HW_ + r * W_ + t0 + gid]     = lA;
        l_out[b * HW_ + r * W_ + t0 + 8 + gid] = lB;
    }

    float* ob = acc_out + (b * C_) * HW_ + r * W_;
    int qq = t0 + gid;
#pragma unroll
    for (int n = 0; n < 8; n++) {
        int cc = n * 8 + 2 * tig;
        ob[cc * HW_ + qq]           = acc[n][0];
        ob[(cc + 1) * HW_ + qq]     = acc[n][1];
        ob[cc * HW_ + qq + 8]       = acc[n][2];
        ob[(cc + 1) * HW_ + qq + 8] = acc[n][3];
    }
}

// ---------------- combine v2 (float4 streams; fused accHT/lHT transpose) ----
__global__ void __launch_bounds__(256) combine2_kernel(
    const float* __restrict__ yin, const float* __restrict__ accHT,
    const float* __restrict__ accW, const float* __restrict__ lHT,
    const float* __restrict__ lW, const float* __restrict__ gamma,
    float* __restrict__ out, float* __restrict__ outT) {
    __shared__ float sH[32][132];
    __shared__ float sL[32][132];
    int h0 = blockIdx.x * 32;
    int bc = blockIdx.y;            // b*64 + c
    int b = bc >> 6;
    int tid = threadIdx.x;

    const float* aT = accHT + bc * HW_;
    const float* lT = lHT + b * HW_;
#pragma unroll
    for (int i = 0; i < 4; i++) {
        int idx = tid + i * 256;
        int w = idx >> 3, hq = idx & 7;
        float4 v = *(const float4*)&aT[w * 128 + h0 + 4 * hq];
        sH[4 * hq + 0][w] = v.x;
        sH[4 * hq + 1][w] = v.y;
        sH[4 * hq + 2][w] = v.z;
        sH[4 * hq + 3][w] = v.w;
        float4 lv = *(const float4*)&lT[w * 128 + h0 + 4 * hq];
        sL[4 * hq + 0][w] = lv.x;
        sL[4 * hq + 1][w] = lv.y;
        sL[4 * hq + 2][w] = lv.z;
        sL[4 * hq + 3][w] = lv.w;
    }
    __syncthreads();

    float g = *gamma;
    const float* yb  = yin + bc * HW_;
    const float* wb  = accW + bc * HW_;
    const float* lwb = lW + b * HW_;
    float* ob = out + bc * HW_;
    int col4 = tid & 31, rowbase = tid >> 5;
#pragma unroll
    for (int j = 0; j < 4; j++) {
        int h_loc = rowbase + 8 * j;
        int base = (h0 + h_loc) * 128 + 4 * col4;
        float4 aH = *(float4*)&sH[h_loc][4 * col4];
        float4 lh = *(float4*)&sL[h_loc][4 * col4];
        float4 yy = *(const float4*)&yb[base];
        float4 aW = *(const float4*)&wb[base];
        float4 lw = *(const float4*)&lwb[base];
        float4 o;
        o.x = yy.x + g * (aH.x + aW.x) / (lh.x + lw.x);
        o.y = yy.y + g * (aH.y + aW.y) / (lh.y + lw.y);
        o.z = yy.z + g * (aH.z + aW.z) / (lh.z + lw.z);
        o.w = yy.w + g * (aH.w + aW.w) / (lh.w + lw.w);
        *(float4*)&ob[base] = o;
        *(float4*)&sH[h_loc][4 * col4] = o;
    }
    if (outT) {
        __syncthreads();
        float* obT = outT + bc * HW_;
#pragma unroll
        for (int i = 0; i < 4; i++) {
            int idx = tid + i * 256;
            int w = idx >> 3, hq = idx & 7;
            float4 ot;
            ot.x = sH[4 * hq + 0][w];
            ot.y = sH[4 * hq + 1][w];
            ot.z = sH[4 * hq + 2][w];
            ot.w = sH[4 * hq + 3][w];
            *(float4*)&obT[w * 128 + h0 + 4 * hq] = ot;
        }
    }
}

// ---------------- pointwise 1x1 conv via tf32 mma (RNA-rounded inputs) -----
#define PW_SMEM_FLOATS (64*136 + 64*68)   // 13056 fl = 52224 B
__global__ void __launch_bounds__(256) pw_kernel(
    const float* __restrict__ in, const float* __restrict__ wpw,
    float* __restrict__ out) {
    extern __shared__ float smem[];
    float* yS = smem;                 // [64][136]
    float* wS = smem + 8704;          // [64][68]
    int bh = blockIdx.x;
    int b = bh >> 7, r = bh & 127;
    int tid = threadIdx.x;
    int lane = tid & 31, wrp = tid >> 5;
    int gid = lane >> 2, tig = lane & 3;
    int t0 = wrp * 16;

#pragma unroll
    for (int i = tid; i < 4096; i += 256) {
        int c = i >> 6, ci = i & 63;
        wS[c * 68 + ci] = tf32f(wpw[i]);
    }
    const float* yb = in + b * C_ * HW_ + r * W_;
#pragma unroll
    for (int i = tid; i < 8192; i += 256) {
        int cin = i >> 7, t = i & 127;
        yS[cin * 136 + t] = tf32f(yb[cin * HW_ + t]);   // RNA round for mma A
    }
    __syncthreads();

    float vacc[8][4];
#pragma unroll
    for (int nt = 0; nt < 8; nt++)
#pragma unroll
        for (int i = 0; i < 4; i++) vacc[nt][i] = 0.f;

#pragma unroll 1
    for (int kt = 0; kt < 8; kt++) {
        int k0 = kt * 8;
        uint32_t a0 = __float_as_uint(yS[(k0 + tig) * 136 + t0 + gid]);
        uint32_t a1 = __float_as_uint(yS[(k0 + tig) * 136 + t0 + 8 + gid]);
        uint32_t a2 = __float_as_uint(yS[(k0 + 4 + tig) * 136 + t0 + gid]);
        uint32_t a3 = __float_as_uint(yS[(k0 + 4 + tig) * 136 + t0 + 8 + gid]);
#pragma unroll
        for (int nt = 0; nt < 8; nt++) {
            uint32_t bf0 = __float_as_uint(wS[(nt * 8 + gid) * 68 + k0 + tig]);
            uint32_t bf1 = __float_as_uint(wS[(nt * 8 + gid) * 68 + k0 + 4 + tig]);
            mma_tf32(vacc[nt], a0, a1, a2, a3, bf0, bf1);
        }
    }

    float* ob = out + (b * C_) * HW_ + r * W_;
    int qq = t0 + gid;
#pragma unroll
    for (int nt = 0; nt < 8; nt++) {
        int cc = nt * 8 + 2 * tig;
        ob[cc * HW_ + qq]           = vacc[nt][0];
        ob[(cc + 1) * HW_ + qq]     = vacc[nt][1];
        ob[cc * HW_ + qq + 8]       = vacc[nt][2];
        ob[(cc + 1) * HW_ + qq + 8] = vacc[nt][3];
    }
}

extern "C" void kernel_launch(void* const* d_in, const int* in_sizes, int n_in,
                              void* d_out, int out_size) {
    const float* x    = (const float*)d_in[0];
    const float* w_dw = (const float*)d_in[1];
    const float* wq   = (const float*)d_in[2];
    const float* wk   = (const float*)d_in[3];
    const float* wv   = (const float*)d_in[4];
    const float* gam  = (const float*)d_in[5];
    const float* w_pw = (const float*)d_in[6];
    float* out = (float*)d_out;

    float *y, *y2, *yT, *accW, *accHT, *lW, *lHT;
    cudaGetSymbolAddress((void**)&y, g_y);
    cudaGetSymbolAddress((void**)&y2, g_y2);
    cudaGetSymbolAddress((void**)&yT, g_yT);
    cudaGetSymbolAddress((void**)&accW, g_accW);
    cudaGetSymbolAddress((void**)&accHT, g_accHT);
    cudaGetSymbolAddress((void**)&lW, g_lW);
    cudaGetSymbolAddress((void**)&lHT, g_lHT);

    const int attn_smem = ATTN_SMEM_FLOATS * 4;
    cudaFuncSetAttribute(attn_kernel,
                         cudaFuncAttributeMaxDynamicSharedMemorySize, attn_smem);
    const int pw_smem = PW_SMEM_FLOATS * 4;
    cudaFuncSetAttribute(pw_kernel,
                         cudaFuncAttributeMaxDynamicSharedMemorySize, pw_smem);

    // dwconv emits y and yT (transposed) in one pass
    dwconv_kernel<<<dim3(4, 4, B_ * C_), dim3(32, 8)>>>(x, w_dw, y, yT);

    // ---- pass 0 ----
    attn_kernel<<<2 * B_ * H_, 256, attn_smem>>>(
        y, yT, wq, wk, wv, accW, accHT, lW, lHT);
    combine2_kernel<<<dim3(4, B_ * C_), 256>>>(
        y, accHT, accW, lHT, lW, gam, y2, yT);   // emits y2 and y2T (in yT buf)

    // ---- pass 1 ----
    attn_kernel<<<2 * B_ * H_, 256, attn_smem>>>(
        y2, yT, wq, wk, wv, accW, accHT, lW, lHT);
    combine2_kernel<<<dim3(4, B_ * C_), 256>>>(
        y2, accHT, accW, lHT, lW, gam, y, nullptr);

    pw_kernel<<<B_ * H_, 256, pw_smem>>>(y, w_pw, out);
}

// round 17
// speedup vs baseline: 1.4478x; 1.4478x over previous
#include <cuda_runtime.h>
#include <cstdint>

#define B_  8
#define C_  64
#define CQ_ 8
#define H_  128
#define W_  128
#define HW_ (H_*W_)            // 16384
#define NPIX_ (B_*HW_)         // 131072
#define NELEM_ (B_*C_*HW_)     // 8388608

typedef unsigned long long u64;

// ---- tf32 helpers ----
__device__ __forceinline__ uint32_t tf32r(float f) {
    uint32_t r; asm("cvt.rna.tf32.f32 %0, %1;" : "=r"(r) : "f"(f));
    return r;
}
__device__ __forceinline__ float tf32f(float f) {
    return __uint_as_float(tf32r(f));
}
__device__ __forceinline__ void mma_tf32(float* d,
    uint32_t a0, uint32_t a1, uint32_t a2, uint32_t a3,
    uint32_t b0, uint32_t b1) {
    asm("mma.sync.aligned.m16n8k8.row.col.f32.tf32.tf32.f32 "
        "{%0,%1,%2,%3}, {%4,%5,%6,%7}, {%8,%9}, {%0,%1,%2,%3};"
        : "+f"(d[0]), "+f"(d[1]), "+f"(d[2]), "+f"(d[3])
        : "r"(a0), "r"(a1), "r"(a2), "r"(a3), "r"(b0), "r"(b1));
}

// ---- scratch (device globals; no allocation allowed) ----
__device__ float g_y[NELEM_];
__device__ float g_y2[NELEM_];
__device__ float g_yT[NELEM_];
__device__ float g_accW[NELEM_];
__device__ float g_accHT[NELEM_];
__device__ float g_lW[NPIX_];
__device__ float g_lHT[NPIX_];

// ---------------- depthwise 3x3 conv, pad 1; emits y AND yT ----------------
__global__ void __launch_bounds__(256) dwconv_kernel(
    const float* __restrict__ x, const float* __restrict__ wdw,
    float* __restrict__ y, float* __restrict__ yT) {
    __shared__ float tile[34][35];
    __shared__ float oT[32][33];
    int p = blockIdx.z;                 // b*C + c
    int c = p & 63;
    int h0 = blockIdx.y * 32, w0 = blockIdx.x * 32;
    int tx = threadIdx.x, ty = threadIdx.y;
    int tid = ty * 32 + tx;
    float wr[9];
#pragma unroll
    for (int i = 0; i < 9; i++) wr[i] = wdw[c * 9 + i];
    const float* xp = x + p * HW_;
#pragma unroll
    for (int idx = tid; idx < 34 * 34; idx += 256) {
        int i = idx / 34, j = idx % 34;
        int hh = h0 - 1 + i, ww = w0 - 1 + j;
        tile[i][j] = (hh >= 0 && hh < 128 && ww >= 0 && ww < 128)
                     ? xp[hh * 128 + ww] : 0.f;
    }
    __syncthreads();
    float* yp = y + p * HW_;
#pragma unroll
    for (int r = 0; r < 4; r++) {
        int i = ty + 8 * r;
        float s = 0.f;
#pragma unroll
        for (int di = 0; di < 3; di++)
#pragma unroll
            for (int dj = 0; dj < 3; dj++)
                s += tile[i + di][tx + dj] * wr[di * 3 + dj];
        yp[(h0 + i) * 128 + w0 + tx] = s;
        oT[i][tx] = s;
    }
    __syncthreads();
    float* ypT = yT + p * HW_;
#pragma unroll
    for (int r = 0; r < 4; r++)
        ypT[(w0 + ty + 8 * r) * 128 + h0 + tx] = oT[tx][ty + 8 * r];
}

// ---------------- fully-mma fused projection + directional attention ------
// Merged W+H: blockIdx.x < 1024 -> W-direction (inA, no mask);
//             else              -> H-direction (inB, diag mask).
// smem: region1 [0,14144): yS[64][136] | wvS[64][68] | wS[16][68]
//       after projection sync: svT[128][72] at [0,9216), sqk[128][20] at [9216,11776)
#define REG1_F 14144
#define ATTN_SMEM_FLOATS REG1_F            // 14144 fl = 56576 B
__global__ void __launch_bounds__(256, 3) attn_kernel(
    const float* __restrict__ inA, const float* __restrict__ inB,
    const float* __restrict__ wq, const float* __restrict__ wk,
    const float* __restrict__ wv,
    float* __restrict__ accA, float* __restrict__ accB,
    float* __restrict__ lA_out, float* __restrict__ lB_out) {
    extern __shared__ float smem[];
    float* yS  = smem;                       // [64][136]
    float* wvS = smem + 8704;                // [64][68]
    float* wS  = smem + 13056;               // [16][68]: q rows 0-7, k rows 8-15
    float (*svT)[72] = (float(*)[72])smem;   // aliases yS after projection
    float* sqk = smem + 9216;                // [128][20], after projection sync

    int half = blockIdx.x >> 10;
    int bh = blockIdx.x & 1023;
    const float* y = half ? inB : inA;
    float* acc_out = half ? accB : accA;
    float* l_out   = half ? lB_out : lA_out;
    int mask_diag  = half;

    int b = bh >> 7, r = bh & 127;
    int tid = threadIdx.x;
    int lane = tid & 31, wrp = tid >> 5;
    int gid = lane >> 2, tig = lane & 3;
    int t0 = wrp * 16;

    // ---- Stage 0: weights (tf32-rounded) + y row ----
#pragma unroll
    for (int i = tid; i < 1024; i += 256) {
        float w = (i < 512) ? wq[i] : wk[i - 512];
        int o = i >> 6, ci = i & 63;
        wS[o * 68 + ci] = tf32f(w);
    }
#pragma unroll
    for (int i = tid; i < 4096; i += 256) {
        int c = i >> 6, ci = i & 63;
        wvS[c * 68 + ci] = tf32f(wv[i]);
    }
    const float* yb = y + b * C_ * HW_ + r * W_;
#pragma unroll
    for (int i = tid; i < 8192; i += 256) {
        int cin = i >> 7, t = i & 127;
        yS[cin * 136 + t] = yb[cin * HW_ + t];
    }
    __syncthreads();

    // ---- Projection: q,k,v via tf32 mma (shared A-frags from yS) ----
    float vacc[8][4];
#pragma unroll
    for (int nt = 0; nt < 8; nt++)
#pragma unroll
        for (int i = 0; i < 4; i++) vacc[nt][i] = 0.f;
    float qacc[4] = {0.f, 0.f, 0.f, 0.f};
    float kacc[4] = {0.f, 0.f, 0.f, 0.f};

#pragma unroll 1
    for (int kt = 0; kt < 8; kt++) {
        int k0 = kt * 8;
        uint32_t a0 = __float_as_uint(yS[(k0 + tig) * 136 + t0 + gid]);
        uint32_t a1 = __float_as_uint(yS[(k0 + tig) * 136 + t0 + 8 + gid]);
        uint32_t a2 = __float_as_uint(yS[(k0 + 4 + tig) * 136 + t0 + gid]);
        uint32_t a3 = __float_as_uint(yS[(k0 + 4 + tig) * 136 + t0 + 8 + gid]);
        uint32_t bq0 = __float_as_uint(wS[gid * 68 + k0 + tig]);
        uint32_t bq1 = __float_as_uint(wS[gid * 68 + k0 + 4 + tig]);
        mma_tf32(qacc, a0, a1, a2, a3, bq0, bq1);
        uint32_t bk0 = __float_as_uint(wS[(8 + gid) * 68 + k0 + tig]);
        uint32_t bk1 = __float_as_uint(wS[(8 + gid) * 68 + k0 + 4 + tig]);
        mma_tf32(kacc, a0, a1, a2, a3, bk0, bk1);
#pragma unroll
        for (int nt = 0; nt < 8; nt++) {
            uint32_t bf0 = __float_as_uint(wvS[(nt * 8 + gid) * 68 + k0 + tig]);
            uint32_t bf1 = __float_as_uint(wvS[(nt * 8 + gid) * 68 + k0 + 4 + tig]);
            mma_tf32(vacc[nt], a0, a1, a2, a3, bf0, bf1);
        }
    }
    __syncthreads();   // all region1 reads complete; svT/sqk may overwrite

    // ---- Epilogues: q,k -> sqk ; v -> svT ----
    *(float2*)&sqk[(t0 + gid) * 20 + 8 + 2 * tig]     = make_float2(qacc[0], qacc[1]);
    *(float2*)&sqk[(t0 + 8 + gid) * 20 + 8 + 2 * tig] = make_float2(qacc[2], qacc[3]);
    *(float2*)&sqk[(t0 + gid) * 20 + 2 * tig]         = make_float2(kacc[0], kacc[1]);
    *(float2*)&sqk[(t0 + 8 + gid) * 20 + 2 * tig]     = make_float2(kacc[2], kacc[3]);
#pragma unroll
    for (int nt = 0; nt < 8; nt++) {
        int cc = nt * 8 + 2 * tig;
        *(float2*)&svT[t0 + gid][cc]     = make_float2(vacc[nt][0], vacc[nt][1]);
        *(float2*)&svT[t0 + 8 + gid][cc] = make_float2(vacc[nt][2], vacc[nt][3]);
    }
    __syncthreads();

    // ---- Fused QK -> exp -> permute -> PV ----
    uint32_t qa0 = __float_as_uint(sqk[(t0 + gid) * 20 + 8 + tig]);
    uint32_t qa1 = __float_as_uint(sqk[(t0 + 8 + gid) * 20 + 8 + tig]);
    uint32_t qa2 = __float_as_uint(sqk[(t0 + gid) * 20 + 12 + tig]);
    uint32_t qa3 = __float_as_uint(sqk[(t0 + 8 + gid) * 20 + 12 + tig]);

    float acc[8][4];
#pragma unroll
    for (int n = 0; n < 8; n++)
#pragma unroll
        for (int i = 0; i < 4; i++) acc[n][i] = 0.f;
    float lA = 0.f, lB = 0.f;
    int srcA = (lane & ~3) | (tig >> 1);
    int srcB = srcA | 2;
    bool odd = tig & 1;

#pragma unroll 1
    for (int nt = 0; nt < 16; nt++) {
        int n0 = nt * 8;
        uint32_t kb0 = __float_as_uint(sqk[(n0 + gid) * 20 + tig]);
        uint32_t kb1 = __float_as_uint(sqk[(n0 + gid) * 20 + 4 + tig]);
        float e[4] = {0.f, 0.f, 0.f, 0.f};
        mma_tf32(e, qa0, qa1, qa2, qa3, kb0, kb1);
        float p0 = __expf(e[0]), p1 = __expf(e[1]);
        float p2 = __expf(e[2]), p3 = __expf(e[3]);
        if (mask_diag) {
            int c0 = n0 + 2 * tig;
            int r0 = t0 + gid, r1 = t0 + 8 + gid;
            if (c0 == r0)     p0 = 0.f;
            if (c0 + 1 == r0) p1 = 0.f;
            if (c0 == r1)     p2 = 0.f;
            if (c0 + 1 == r1) p3 = 0.f;
        }
        lA += p0 + p1; lB += p2 + p3;
        float s0 = __shfl_sync(0xffffffffu, p0, srcA);
        float s1 = __shfl_sync(0xffffffffu, p1, srcA);
        float s2 = __shfl_sync(0xffffffffu, p2, srcA);
        float s3 = __shfl_sync(0xffffffffu, p3, srcA);
        float s4 = __shfl_sync(0xffffffffu, p0, srcB);
        float s5 = __shfl_sync(0xffffffffu, p1, srcB);
        float s6 = __shfl_sync(0xffffffffu, p2, srcB);
        float s7 = __shfl_sync(0xffffffffu, p3, srcB);
        uint32_t a0 = __float_as_uint(odd ? s1 : s0);
        uint32_t a1 = __float_as_uint(odd ? s3 : s2);
        uint32_t a2 = __float_as_uint(odd ? s5 : s4);
        uint32_t a3 = __float_as_uint(odd ? s7 : s6);
#pragma unroll
        for (int n = 0; n < 8; n++) {
            uint32_t bf0 = __float_as_uint(svT[n0 + tig][n * 8 + gid]);
            uint32_t bf1 = __float_as_uint(svT[n0 + 4 + tig][n * 8 + gid]);
            mma_tf32(acc[n], a0, a1, a2, a3, bf0, bf1);
        }
    }

    // ---- l reduction (across tig) + stores ----
    lA += __shfl_xor_sync(0xffffffffu, lA, 1);
    lA += __shfl_xor_sync(0xffffffffu, lA, 2);
    lB += __shfl_xor_sync(0xffffffffu, lB, 1);
    lB += __shfl_xor_sync(0xffffffffu, lB, 2);
    if (tig == 0) {
        l_out[b * HW_ + r * W_ + t0 + gid]     = lA;
        l_out[b * HW_ + r * W_ + t0 + 8 + gid] = lB;
    }

    float* ob = acc_out + (b * C_) * HW_ + r * W_;
    int qq = t0 + gid;
#pragma unroll
    for (int n = 0; n < 8; n++) {
        int cc = n * 8 + 2 * tig;
        ob[cc * HW_ + qq]           = acc[n][0];
        ob[(cc + 1) * HW_ + qq]     = acc[n][1];
        ob[cc * HW_ + qq + 8]       = acc[n][2];
        ob[(cc + 1) * HW_ + qq + 8] = acc[n][3];
    }
}

// ---------------- combine v2 (float4 streams; fused accHT/lHT transpose) ----
__global__ void __launch_bounds__(256) combine2_kernel(
    const float* __restrict__ yin, const float* __restrict__ accHT,
    const float* __restrict__ accW, const float* __restrict__ lHT,
    const float* __restrict__ lW, const float* __restrict__ gamma,
    float* __restrict__ out, float* __restrict__ outT) {
    __shared__ float sH[32][132];
    __shared__ float sL[32][132];
    int h0 = blockIdx.x * 32;
    int bc = blockIdx.y;            // b*64 + c
    int b = bc >> 6;
    int tid = threadIdx.x;

    const float* aT = accHT + bc * HW_;
    const float* lT = lHT + b * HW_;
#pragma unroll
    for (int i = 0; i < 4; i++) {
        int idx = tid + i * 256;
        int w = idx >> 3, hq = idx & 7;
        float4 v = *(const float4*)&aT[w * 128 + h0 + 4 * hq];
        sH[4 * hq + 0][w] = v.x;
        sH[4 * hq + 1][w] = v.y;
        sH[4 * hq + 2][w] = v.z;
        sH[4 * hq + 3][w] = v.w;
        float4 lv = *(const float4*)&lT[w * 128 + h0 + 4 * hq];
        sL[4 * hq + 0][w] = lv.x;
        sL[4 * hq + 1][w] = lv.y;
        sL[4 * hq + 2][w] = lv.z;
        sL[4 * hq + 3][w] = lv.w;
    }
    __syncthreads();

    float g = *gamma;
    const float* yb  = yin + bc * HW_;
    const float* wb  = accW + bc * HW_;
    const float* lwb = lW + b * HW_;
    float* ob = out + bc * HW_;
    int col4 = tid & 31, rowbase = tid >> 5;
#pragma unroll
    for (int j = 0; j < 4; j++) {
        int h_loc = rowbase + 8 * j;
        int base = (h0 + h_loc) * 128 + 4 * col4;
        float4 aH = *(float4*)&sH[h_loc][4 * col4];
        float4 lh = *(float4*)&sL[h_loc][4 * col4];
        float4 yy = *(const float4*)&yb[base];
        float4 aW = *(const float4*)&wb[base];
        float4 lw = *(const float4*)&lwb[base];
        float4 o;
        o.x = yy.x + g * (aH.x + aW.x) / (lh.x + lw.x);
        o.y = yy.y + g * (aH.y + aW.y) / (lh.y + lw.y);
        o.z = yy.z + g * (aH.z + aW.z) / (lh.z + lw.z);
        o.w = yy.w + g * (aH.w + aW.w) / (lh.w + lw.w);
        *(float4*)&ob[base] = o;
        *(float4*)&sH[h_loc][4 * col4] = o;
    }
    if (outT) {
        __syncthreads();
        float* obT = outT + bc * HW_;
#pragma unroll
        for (int i = 0; i < 4; i++) {
            int idx = tid + i * 256;
            int w = idx >> 3, hq = idx & 7;
            float4 ot;
            ot.x = sH[4 * hq + 0][w];
            ot.y = sH[4 * hq + 1][w];
            ot.z = sH[4 * hq + 2][w];
            ot.w = sH[4 * hq + 3][w];
            *(float4*)&obT[w * 128 + h0 + 4 * hq] = ot;
        }
    }
}

// ---------------- pointwise 1x1 conv via tf32 mma (RNA-rounded inputs) -----
#define PW_SMEM_FLOATS (64*136 + 64*68)   // 13056 fl = 52224 B
__global__ void __launch_bounds__(256) pw_kernel(
    const float* __restrict__ in, const float* __restrict__ wpw,
    float* __restrict__ out) {
    extern __shared__ float smem[];
    float* yS = smem;                 // [64][136]
    float* wS = smem + 8704;          // [64][68]
    int bh = blockIdx.x;
    int b = bh >> 7, r = bh & 127;
    int tid = threadIdx.x;
    int lane = tid & 31, wrp = tid >> 5;
    int gid = lane >> 2, tig = lane & 3;
    int t0 = wrp * 16;

#pragma unroll
    for (int i = tid; i < 4096; i += 256) {
        int c = i >> 6, ci = i & 63;
        wS[c * 68 + ci] = tf32f(wpw[i]);
    }
    const float* yb = in + b * C_ * HW_ + r * W_;
#pragma unroll
    for (int i = tid; i < 8192; i += 256) {
        int cin = i >> 7, t = i & 127;
        yS[cin * 136 + t] = tf32f(yb[cin * HW_ + t]);   // RNA round for mma A
    }
    __syncthreads();

    float vacc[8][4];
#pragma unroll
    for (int nt = 0; nt < 8; nt++)
#pragma unroll
        for (int i = 0; i < 4; i++) vacc[nt][i] = 0.f;

#pragma unroll 1
    for (int kt = 0; kt < 8; kt++) {
        int k0 = kt * 8;
        uint32_t a0 = __float_as_uint(yS[(k0 + tig) * 136 + t0 + gid]);
        uint32_t a1 = __float_as_uint(yS[(k0 + tig) * 136 + t0 + 8 + gid]);
        uint32_t a2 = __float_as_uint(yS[(k0 + 4 + tig) * 136 + t0 + gid]);
        uint32_t a3 = __float_as_uint(yS[(k0 + 4 + tig) * 136 + t0 + 8 + gid]);
#pragma unroll
        for (int nt = 0; nt < 8; nt++) {
            uint32_t bf0 = __float_as_uint(wS[(nt * 8 + gid) * 68 + k0 + tig]);
            uint32_t bf1 = __float_as_uint(wS[(nt * 8 + gid) * 68 + k0 + 4 + tig]);
            mma_tf32(vacc[nt], a0, a1, a2, a3, bf0, bf1);
        }
    }

    float* ob = out + (b * C_) * HW_ + r * W_;
    int qq = t0 + gid;
#pragma unroll
    for (int nt = 0; nt < 8; nt++) {
        int cc = nt * 8 + 2 * tig;
        ob[cc * HW_ + qq]           = vacc[nt][0];
        ob[(cc + 1) * HW_ + qq]     = vacc[nt][1];
        ob[cc * HW_ + qq + 8]       = vacc[nt][2];
        ob[(cc + 1) * HW_ + qq + 8] = vacc[nt][3];
    }
}

extern "C" void kernel_launch(void* const* d_in, const int* in_sizes, int n_in,
                              void* d_out, int out_size) {
    const float* x    = (const float*)d_in[0];
    const float* w_dw = (const float*)d_in[1];
    const float* wq   = (const float*)d_in[2];
    const float* wk   = (const float*)d_in[3];
    const float* wv   = (const float*)d_in[4];
    const float* gam  = (const float*)d_in[5];
    const float* w_pw = (const float*)d_in[6];
    float* out = (float*)d_out;

    float *y, *y2, *yT, *accW, *accHT, *lW, *lHT;
    cudaGetSymbolAddress((void**)&y, g_y);
    cudaGetSymbolAddress((void**)&y2, g_y2);
    cudaGetSymbolAddress((void**)&yT, g_yT);
    cudaGetSymbolAddress((void**)&accW, g_accW);
    cudaGetSymbolAddress((void**)&accHT, g_accHT);
    cudaGetSymbolAddress((void**)&lW, g_lW);
    cudaGetSymbolAddress((void**)&lHT, g_lHT);

    const int attn_smem = ATTN_SMEM_FLOATS * 4;
    cudaFuncSetAttribute(attn_kernel,
                         cudaFuncAttributeMaxDynamicSharedMemorySize, attn_smem);
    const int pw_smem = PW_SMEM_FLOATS * 4;
    cudaFuncSetAttribute(pw_kernel,
                         cudaFuncAttributeMaxDynamicSharedMemorySize, pw_smem);

    // dwconv emits y and yT (transposed) in one pass
    dwconv_kernel<<<dim3(4, 4, B_ * C_), dim3(32, 8)>>>(x, w_dw, y, yT);

    // ---- pass 0 ----
    attn_kernel<<<2 * B_ * H_, 256, attn_smem>>>(
        y, yT, wq, wk, wv, accW, accHT, lW, lHT);
    combine2_kernel<<<dim3(4, B_ * C_), 256>>>(
        y, accHT, accW, lHT, lW, gam, y2, yT);   // emits y2 and y2T (in yT buf)

    // ---- pass 1 ----
    attn_kernel<<<2 * B_ * H_, 256, attn_smem>>>(
        y2, yT, wq, wk, wv, accW, accHT, lW, lHT);
    combine2_kernel<<<dim3(4, B_ * C_), 256>>>(
        y2, accHT, accW, lHT, lW, gam, y, nullptr);

    pw_kernel<<<B_ * H_, 256, pw_smem>>>(y, w_pw, out);
}